// round 1
// baseline (speedup 1.0000x reference)
#include <cuda_runtime.h>
#include <math.h>

// Problem constants
#define TT   4096      // tokens = B*S
#define DM   1024      // d_model
#define HH   4096      // hidden
#define NE   8         // experts
#define NSEG 9         // 8 experts + shared (segment 8)
#define CAP  4096      // per-segment token capacity (worst case: all tokens -> one expert)

// Scratch (allocation-free rule: __device__ globals)
__device__ int   g_cnt[NSEG];
__device__ int   g_row[NSEG][CAP];
__device__ float g_gt [NSEG][CAP];
__device__ float g_h  [150994944];   // NSEG * CAP * HH floats (~604 MB)

// ---------------------------------------------------------------------------
// init: zero output, reset per-expert counters, enroll all tokens on the
// shared-expert segment (index NE) with gate 1.0
// ---------------------------------------------------------------------------
__global__ void init_kernel(float* __restrict__ out) {
    int idx    = blockIdx.x * blockDim.x + threadIdx.x;
    int stride = gridDim.x * blockDim.x;
    for (int i = idx; i < TT * DM; i += stride) out[i] = 0.f;
    for (int t = idx; t < TT; t += stride) { g_row[NE][t] = t; g_gt[NE][t] = 1.f; }
    if (idx < NE)       g_cnt[idx] = 0;
    else if (idx == NE) g_cnt[NE]  = TT;
}

// ---------------------------------------------------------------------------
// gating: one warp per token. 8 dot products of length 1024, top-2 (jax
// tie-break: lower index wins), softmax over the two, scatter into lists.
// ---------------------------------------------------------------------------
__global__ void gate_kernel(const float* __restrict__ x, const float* __restrict__ gw) {
    int gtid = blockIdx.x * blockDim.x + threadIdx.x;
    int t = gtid >> 5, lane = gtid & 31;
    if (t >= TT) return;
    const float* xr = x + (size_t)t * DM;
    float acc[NE];
#pragma unroll
    for (int e = 0; e < NE; e++) acc[e] = 0.f;
    for (int k = lane; k < DM; k += 32) {
        float xv = xr[k];
#pragma unroll
        for (int e = 0; e < NE; e++) acc[e] += xv * gw[e * DM + k];
    }
#pragma unroll
    for (int e = 0; e < NE; e++) {
#pragma unroll
        for (int o = 16; o > 0; o >>= 1) acc[e] += __shfl_xor_sync(0xffffffffu, acc[e], o);
    }
    if (lane == 0) {
        int i0 = 0; float v0 = acc[0];
#pragma unroll
        for (int e = 1; e < NE; e++) if (acc[e] > v0) { v0 = acc[e]; i0 = e; }
        int i1 = -1; float v1 = -1e30f;
#pragma unroll
        for (int e = 0; e < NE; e++) if (e != i0 && acc[e] > v1) { v1 = acc[e]; i1 = e; }
        float ex = expf(v1 - v0);            // v0 >= v1, stable
        float g0 = 1.f / (1.f + ex);
        float g1 = ex  / (1.f + ex);
        int p0 = atomicAdd(&g_cnt[i0], 1); g_row[i0][p0] = t; g_gt[i0][p0] = g0;
        int p1 = atomicAdd(&g_cnt[i1], 1); g_row[i1][p1] = t; g_gt[i1][p1] = g1;
    }
}

// ---------------------------------------------------------------------------
// GEMM1 (grouped, gathered A): h = silu( x[rows] @ W1^T ),  K = DM
// C tile 128x128, K-tile 16, 256 threads, 8x8 per-thread microtile.
// ---------------------------------------------------------------------------
__global__ __launch_bounds__(256, 2) void gemm1_kernel(
        const float* __restrict__ x,
        const float* __restrict__ sw1,
        const float* __restrict__ ew1) {
    const int e   = blockIdx.z;
    const int cnt = g_cnt[e];
    const int m0  = blockIdx.y * 128;
    if (m0 >= cnt) return;
    const int n0  = blockIdx.x * 128;
    const float* __restrict__ W = (e == NE) ? sw1 : (ew1 + (size_t)e * HH * DM);

    __shared__ float As[16][128];
    __shared__ float Bs[16][128];
    __shared__ int   rIdx[128];

    const int tid = threadIdx.x;
    if (tid < 128) { int m = m0 + tid; rIdx[tid] = (m < cnt) ? g_row[e][m] : -1; }
    __syncthreads();

    const int lr = tid >> 2;        // 0..63
    const int kq = (tid & 3) * 4;   // 0,4,8,12
    const int tm = tid >> 4;        // 0..15
    const int tn = tid & 15;        // 0..15

    float acc[8][8];
#pragma unroll
    for (int i = 0; i < 8; i++)
#pragma unroll
        for (int j = 0; j < 8; j++) acc[i][j] = 0.f;

    for (int kt = 0; kt < DM; kt += 16) {
#pragma unroll
        for (int h = 0; h < 2; h++) {
            int r = lr + h * 64;
            int ridx = rIdx[r];
            float4 v = make_float4(0.f, 0.f, 0.f, 0.f);
            if (ridx >= 0) v = *reinterpret_cast<const float4*>(x + (size_t)ridx * DM + kt + kq);
            As[kq + 0][r] = v.x; As[kq + 1][r] = v.y; As[kq + 2][r] = v.z; As[kq + 3][r] = v.w;
        }
#pragma unroll
        for (int h = 0; h < 2; h++) {
            int r = lr + h * 64;
            float4 v = *reinterpret_cast<const float4*>(W + (size_t)(n0 + r) * DM + kt + kq);
            Bs[kq + 0][r] = v.x; Bs[kq + 1][r] = v.y; Bs[kq + 2][r] = v.z; Bs[kq + 3][r] = v.w;
        }
        __syncthreads();
#pragma unroll
        for (int k = 0; k < 16; k++) {
            float a[8], b[8];
#pragma unroll
            for (int i = 0; i < 8; i++) a[i] = As[k][tm * 8 + i];
#pragma unroll
            for (int j = 0; j < 8; j++) b[j] = Bs[k][tn * 8 + j];
#pragma unroll
            for (int i = 0; i < 8; i++)
#pragma unroll
                for (int j = 0; j < 8; j++) acc[i][j] += a[i] * b[j];
        }
        __syncthreads();
    }

    // epilogue: SiLU, store to scratch
#pragma unroll
    for (int i = 0; i < 8; i++) {
        int m = m0 + tm * 8 + i;
        if (m < cnt) {
            float* dst = g_h + ((size_t)e * CAP + m) * HH + n0 + tn * 8;
            float o[8];
#pragma unroll
            for (int j = 0; j < 8; j++) {
                float v = acc[i][j];
                o[j] = v / (1.f + expf(-v));
            }
            *reinterpret_cast<float4*>(dst)     = make_float4(o[0], o[1], o[2], o[3]);
            *reinterpret_cast<float4*>(dst + 4) = make_float4(o[4], o[5], o[6], o[7]);
        }
    }
}

// ---------------------------------------------------------------------------
// GEMM2 (grouped, dense A in scratch): out[tok] += gate * ( h @ W2^T ), K = HH
// ---------------------------------------------------------------------------
__global__ __launch_bounds__(256, 2) void gemm2_kernel(
        const float* __restrict__ sw2,
        const float* __restrict__ ew2,
        float* __restrict__ out) {
    const int e   = blockIdx.z;
    const int cnt = g_cnt[e];
    const int m0  = blockIdx.y * 128;
    if (m0 >= cnt) return;
    const int n0  = blockIdx.x * 128;
    const float* __restrict__ W = (e == NE) ? sw2 : (ew2 + (size_t)e * DM * HH);
    const float* __restrict__ A = g_h + (size_t)e * CAP * HH;

    __shared__ float As[16][128];
    __shared__ float Bs[16][128];
    __shared__ int   rIdx[128];
    __shared__ float gVal[128];

    const int tid = threadIdx.x;
    if (tid < 128) {
        int m = m0 + tid; bool v = (m < cnt);
        rIdx[tid] = v ? g_row[e][m] : -1;
        gVal[tid] = v ? g_gt[e][m]  : 0.f;
    }
    __syncthreads();

    const int lr = tid >> 2;
    const int kq = (tid & 3) * 4;
    const int tm = tid >> 4;
    const int tn = tid & 15;

    float acc[8][8];
#pragma unroll
    for (int i = 0; i < 8; i++)
#pragma unroll
        for (int j = 0; j < 8; j++) acc[i][j] = 0.f;

    for (int kt = 0; kt < HH; kt += 16) {
#pragma unroll
        for (int h = 0; h < 2; h++) {
            int r = lr + h * 64;
            float4 v = make_float4(0.f, 0.f, 0.f, 0.f);
            if (m0 + r < cnt) v = *reinterpret_cast<const float4*>(A + (size_t)(m0 + r) * HH + kt + kq);
            As[kq + 0][r] = v.x; As[kq + 1][r] = v.y; As[kq + 2][r] = v.z; As[kq + 3][r] = v.w;
        }
#pragma unroll
        for (int h = 0; h < 2; h++) {
            int r = lr + h * 64;
            float4 v = *reinterpret_cast<const float4*>(W + (size_t)(n0 + r) * HH + kt + kq);
            Bs[kq + 0][r] = v.x; Bs[kq + 1][r] = v.y; Bs[kq + 2][r] = v.z; Bs[kq + 3][r] = v.w;
        }
        __syncthreads();
#pragma unroll
        for (int k = 0; k < 16; k++) {
            float a[8], b[8];
#pragma unroll
            for (int i = 0; i < 8; i++) a[i] = As[k][tm * 8 + i];
#pragma unroll
            for (int j = 0; j < 8; j++) b[j] = Bs[k][tn * 8 + j];
#pragma unroll
            for (int i = 0; i < 8; i++)
#pragma unroll
                for (int j = 0; j < 8; j++) acc[i][j] += a[i] * b[j];
        }
        __syncthreads();
    }

    // epilogue: scale by gate, atomic-accumulate into the token's output row
#pragma unroll
    for (int i = 0; i < 8; i++) {
        int ml = tm * 8 + i;
        int m  = m0 + ml;
        if (m < cnt) {
            int   tok = rIdx[ml];
            float gv  = gVal[ml];
            float* op = out + (size_t)tok * DM + n0 + tn * 8;
#pragma unroll
            for (int j = 0; j < 8; j++) atomicAdd(op + j, acc[i][j] * gv);
        }
    }
}

// ---------------------------------------------------------------------------
extern "C" void kernel_launch(void* const* d_in, const int* in_sizes, int n_in,
                              void* d_out, int out_size) {
    const float* x   = (const float*)d_in[0];
    const float* sw1 = (const float*)d_in[1];
    const float* sw2 = (const float*)d_in[2];
    const float* ew1 = (const float*)d_in[3];
    const float* ew2 = (const float*)d_in[4];
    const float* gw  = (const float*)d_in[5];
    float* out = (float*)d_out;

    init_kernel<<<256, 256>>>(out);
    gate_kernel<<<(TT * 32 + 255) / 256, 256>>>(x, gw);
    gemm1_kernel<<<dim3(HH / 128, CAP / 128, NSEG), 256>>>(x, sw1, ew1);
    gemm2_kernel<<<dim3(DM / 128, CAP / 128, NSEG), 256>>>(sw2, ew2, out);
}

// round 4
// speedup vs baseline: 2.5781x; 2.5781x over previous
#include <cuda_runtime.h>
#include <cuda_bf16.h>
#include <math.h>
#include <stdint.h>

#define TT   4096
#define DM   1024
#define HH   4096
#define NE   8
#define NSEG 9
#define CAP  4096

// smem tile geometry: 128 rows x 64 bf16 (128B data), padded to 144B per row
#define TILE_B  (128 * 144)           // 18432
#define STAGE_B (4 * TILE_B)          // 73728
#define SMEM_SZ (2 * STAGE_B)         // 147456

// ---------------- scratch (__device__ globals; allocation-free rule) -------
__device__ int   g_cnt[NSEG];
__device__ int   g_rowmap[NE * CAP];
__device__ int   t_ei[TT * 2];
__device__ int   t_si[TT * 2];
__device__ float t_gv[TT * 2];

__device__ __align__(16) __nv_bfloat16 g_xh[(size_t)NSEG * CAP * DM];
__device__ __align__(16) __nv_bfloat16 g_xl[(size_t)NSEG * CAP * DM];
__device__ __align__(16) __nv_bfloat16 g_w1h[(size_t)NSEG * HH * DM];
__device__ __align__(16) __nv_bfloat16 g_w1l[(size_t)NSEG * HH * DM];
__device__ __align__(16) __nv_bfloat16 g_w2h[(size_t)NSEG * DM * HH];
__device__ __align__(16) __nv_bfloat16 g_w2l[(size_t)NSEG * DM * HH];
__device__ __align__(16) __nv_bfloat16 g_hh[(size_t)NSEG * CAP * HH];
__device__ __align__(16) __nv_bfloat16 g_hl[(size_t)NSEG * CAP * HH];
__device__ __align__(16) float         g_y [(size_t)NSEG * CAP * DM];

// ---------------- helpers ---------------------------------------------------
__device__ __forceinline__ uint32_t s2u(const void* p) {
    uint32_t a;
    asm("{ .reg .u64 t; cvta.to.shared.u64 t, %1; cvt.u32.u64 %0, t; }" : "=r"(a) : "l"(p));
    return a;
}
__device__ __forceinline__ void cpasync16(uint32_t dst, const void* src) {
    asm volatile("cp.async.cg.shared.global [%0], [%1], 16;" :: "r"(dst), "l"(src) : "memory");
}
__device__ __forceinline__ void cp_commit() { asm volatile("cp.async.commit_group;" ::: "memory"); }
template <int N> __device__ __forceinline__ void cp_wait() {
    asm volatile("cp.async.wait_group %0;" :: "n"(N) : "memory");
}
__device__ __forceinline__ void ldsm4(uint32_t* r, uint32_t a) {
    asm volatile("ldmatrix.sync.aligned.m8n8.x4.shared.b16 {%0,%1,%2,%3}, [%4];"
                 : "=r"(r[0]), "=r"(r[1]), "=r"(r[2]), "=r"(r[3]) : "r"(a));
}
__device__ __forceinline__ void ldsm2(uint32_t* r, uint32_t a) {
    asm volatile("ldmatrix.sync.aligned.m8n8.x2.shared.b16 {%0,%1}, [%2];"
                 : "=r"(r[0]), "=r"(r[1]) : "r"(a));
}
__device__ __forceinline__ void mma16816(float* c, const uint32_t* a, const uint32_t* b) {
    asm volatile("mma.sync.aligned.m16n8k16.row.col.f32.bf16.bf16.f32 "
                 "{%0,%1,%2,%3}, {%4,%5,%6,%7}, {%8,%9}, {%0,%1,%2,%3};"
                 : "+f"(c[0]), "+f"(c[1]), "+f"(c[2]), "+f"(c[3])
                 : "r"(a[0]), "r"(a[1]), "r"(a[2]), "r"(a[3]), "r"(b[0]), "r"(b[1]));
}
__device__ __forceinline__ void split2(float v, __nv_bfloat16& h, __nv_bfloat16& l) {
    h = __float2bfloat16(v);
    l = __float2bfloat16(v - __bfloat162float(h));
}

// ---------------- reset ------------------------------------------------------
__global__ void reset_k() {
    int i = threadIdx.x;
    if (i < NE) g_cnt[i] = 0;
    if (i == NE) g_cnt[NE] = TT;
}

// ---------------- gating: one warp per token --------------------------------
__global__ void gate_k(const float* __restrict__ x, const float* __restrict__ gw) {
    int gtid = blockIdx.x * blockDim.x + threadIdx.x;
    int t = gtid >> 5, lane = gtid & 31;
    if (t >= TT) return;
    const float* xr = x + (size_t)t * DM;
    float acc[NE];
#pragma unroll
    for (int e = 0; e < NE; e++) acc[e] = 0.f;
    for (int k = lane; k < DM; k += 32) {
        float xv = xr[k];
#pragma unroll
        for (int e = 0; e < NE; e++) acc[e] += xv * gw[e * DM + k];
    }
#pragma unroll
    for (int e = 0; e < NE; e++) {
#pragma unroll
        for (int o = 16; o > 0; o >>= 1) acc[e] += __shfl_xor_sync(0xffffffffu, acc[e], o);
    }
    if (lane == 0) {
        int i0 = 0; float v0 = acc[0];
#pragma unroll
        for (int e = 1; e < NE; e++) if (acc[e] > v0) { v0 = acc[e]; i0 = e; }
        int i1 = -1; float v1 = -1e30f;
#pragma unroll
        for (int e = 0; e < NE; e++) if (e != i0 && acc[e] > v1) { v1 = acc[e]; i1 = e; }
        float ex = expf(v1 - v0);
        float g0 = 1.f / (1.f + ex);
        float g1 = ex / (1.f + ex);
        int p0 = atomicAdd(&g_cnt[i0], 1); g_rowmap[i0 * CAP + p0] = t;
        int p1 = atomicAdd(&g_cnt[i1], 1); g_rowmap[i1 * CAP + p1] = t;
        t_ei[2 * t] = i0; t_si[2 * t] = p0; t_gv[2 * t] = g0;
        t_ei[2 * t + 1] = i1; t_si[2 * t + 1] = p1; t_gv[2 * t + 1] = g1;
    }
}

// ---------------- weight convert fp32 -> bf16 hi/lo --------------------------
__global__ void wcvt_k(const float* __restrict__ sw1, const float* __restrict__ sw2,
                       const float* __restrict__ ew1, const float* __restrict__ ew2) {
    int seg = blockIdx.y, wsel = blockIdx.z;
    size_t segoff = (size_t)seg * HH * DM;
    size_t i4 = (size_t)blockIdx.x * 256 + threadIdx.x;
    const float* src;
    __nv_bfloat16 *dh, *dl;
    if (wsel == 0) {
        src = (seg == NE) ? sw1 : (ew1 + segoff);
        dh = g_w1h + segoff; dl = g_w1l + segoff;
    } else {
        src = (seg == NE) ? sw2 : (ew2 + segoff);
        dh = g_w2h + segoff; dl = g_w2l + segoff;
    }
    float4 v = ((const float4*)src)[i4];
    __nv_bfloat16 h0, l0, h1, l1, h2, l2, h3, l3;
    split2(v.x, h0, l0); split2(v.y, h1, l1); split2(v.z, h2, l2); split2(v.w, h3, l3);
    __nv_bfloat162* ph = (__nv_bfloat162*)(dh + i4 * 4);
    __nv_bfloat162* pl = (__nv_bfloat162*)(dl + i4 * 4);
    ph[0] = __nv_bfloat162{h0, h1}; ph[1] = __nv_bfloat162{h2, h3};
    pl[0] = __nv_bfloat162{l0, l1}; pl[1] = __nv_bfloat162{l2, l3};
}

// ---------------- gather + convert activations per segment -------------------
__global__ void gather_k(const float* __restrict__ x) {
    int seg = blockIdx.y, slot = blockIdx.x;
    int cnt = g_cnt[seg];
    int pad = (cnt + 127) & ~127;
    if (slot >= pad) return;
    size_t drow = ((size_t)seg * CAP + slot) * DM;
    int i = threadIdx.x;
    __nv_bfloat16 h0, l0, h1, l1, h2, l2, h3, l3;
    if (slot < cnt) {
        int tok = (seg == NE) ? slot : g_rowmap[seg * CAP + slot];
        float4 v = ((const float4*)(x + (size_t)tok * DM))[i];
        split2(v.x, h0, l0); split2(v.y, h1, l1); split2(v.z, h2, l2); split2(v.w, h3, l3);
    } else {
        h0 = l0 = h1 = l1 = h2 = l2 = h3 = l3 = __float2bfloat16(0.f);
    }
    __nv_bfloat162* ph = (__nv_bfloat162*)(g_xh + drow + (size_t)i * 4);
    __nv_bfloat162* pl = (__nv_bfloat162*)(g_xl + drow + (size_t)i * 4);
    ph[0] = __nv_bfloat162{h0, h1}; ph[1] = __nv_bfloat162{h2, h3};
    pl[0] = __nv_bfloat162{l0, l1}; pl[1] = __nv_bfloat162{l2, l3};
}

// ---------------- grouped GEMM via mma.sync (split-bf16, 128x128 tile) -------
// PHASE 1: h = silu(x @ W1^T), K=1024; PHASE 2: y = h @ W2^T, K=4096
template <int PHASE>
__global__ __launch_bounds__(256, 1) void gemm_k() {
    constexpr int KLEN = (PHASE == 1) ? DM : HH;
    constexpr int NDIM = (PHASE == 1) ? HH : DM;
    constexpr int NC   = KLEN / 64;

    const int seg = blockIdx.z;
    const int cnt = g_cnt[seg];
    const int m0  = blockIdx.y * 128;
    if (m0 >= cnt) return;
    const int n0  = blockIdx.x * 128;

    extern __shared__ char smem[];
    const uint32_t sb = s2u(smem);

    const int tid  = threadIdx.x;
    const int lane = tid & 31;
    const int warp = tid >> 5;
    const int wm   = (warp & 1) * 64;   // warp m-base within tile
    const int wn   = (warp >> 1) * 32;  // warp n-base within tile

    const __nv_bfloat16* srcs[4];
    if (PHASE == 1) {
        srcs[0] = g_xh  + ((size_t)seg * CAP  + m0) * KLEN;
        srcs[1] = g_xl  + ((size_t)seg * CAP  + m0) * KLEN;
        srcs[2] = g_w1h + ((size_t)seg * NDIM + n0) * KLEN;
        srcs[3] = g_w1l + ((size_t)seg * NDIM + n0) * KLEN;
    } else {
        srcs[0] = g_hh  + ((size_t)seg * CAP  + m0) * KLEN;
        srcs[1] = g_hl  + ((size_t)seg * CAP  + m0) * KLEN;
        srcs[2] = g_w2h + ((size_t)seg * NDIM + n0) * KLEN;
        srcs[3] = g_w2l + ((size_t)seg * NDIM + n0) * KLEN;
    }

    // load one 128x64 bf16 K-chunk per operand tile: 1024 x 16B chunks per tile
    auto issue = [&](int c) {
        uint32_t base = sb + (c & 1) * STAGE_B;
#pragma unroll
        for (int tI = 0; tI < 4; tI++) {
            const __nv_bfloat16* s = srcs[tI];
#pragma unroll
            for (int it = 0; it < 4; it++) {
                int o = tid + it * 256;          // 0..1023
                int row = o >> 3, q = o & 7;     // row 0..127, q 0..7 (16B each)
                cpasync16(base + tI * TILE_B + row * 144 + q * 16,
                          s + (size_t)row * KLEN + c * 64 + q * 8);
            }
        }
        cp_commit();
    };

    float acc[4][4][4];
#pragma unroll
    for (int mi = 0; mi < 4; mi++)
#pragma unroll
        for (int ni = 0; ni < 4; ni++)
#pragma unroll
            for (int r = 0; r < 4; r++) acc[mi][ni][r] = 0.f;

    issue(0);

    for (int c = 0; c < NC; c++) {
        if (c + 1 < NC) { issue(c + 1); cp_wait<1>(); }
        else            { cp_wait<0>(); }
        __syncthreads();

        uint32_t Ah = sb + (c & 1) * STAGE_B;
        uint32_t Al = Ah + TILE_B;
        uint32_t Bh = Ah + 2 * TILE_B;
        uint32_t Bl = Ah + 3 * TILE_B;

#pragma unroll
        for (int ks = 0; ks < 4; ks++) {
            uint32_t ah[4][4], al[4][4], bh[4][2], bl[4][2];
            const uint32_t acol = ks * 32 + (lane >> 4) * 16;
            const uint32_t bcol = ks * 32 + ((lane >> 3) & 1) * 16;
#pragma unroll
            for (int mi = 0; mi < 4; mi++) {
                uint32_t roff = (wm + mi * 16 + (lane & 15)) * 144;
                ldsm4(ah[mi], Ah + roff + acol);
                ldsm4(al[mi], Al + roff + acol);
            }
#pragma unroll
            for (int ni = 0; ni < 4; ni++) {
                uint32_t roff = (wn + ni * 8 + (lane & 7)) * 144;
                ldsm2(bh[ni], Bh + roff + bcol);
                ldsm2(bl[ni], Bl + roff + bcol);
            }
#pragma unroll
            for (int mi = 0; mi < 4; mi++)
#pragma unroll
                for (int ni = 0; ni < 4; ni++) {
                    mma16816(acc[mi][ni], ah[mi], bh[ni]);
                    mma16816(acc[mi][ni], ah[mi], bl[ni]);
                    mma16816(acc[mi][ni], al[mi], bh[ni]);
                }
        }
        __syncthreads();
    }

    // ---- epilogue: regs -> smem (f32, stride 132) -> coalesced gmem ----
    float* SF = (float*)smem;
#pragma unroll
    for (int mi = 0; mi < 4; mi++)
#pragma unroll
        for (int ni = 0; ni < 4; ni++)
#pragma unroll
            for (int r = 0; r < 4; r++) {
                int row = wm + mi * 16 + (lane >> 2) + (r >> 1) * 8;
                int col = wn + ni * 8 + (lane & 3) * 2 + (r & 1);
                float v = acc[mi][ni][r];
                if (PHASE == 1) v = v / (1.f + expf(-v));
                SF[row * 132 + col] = v;
            }
    __syncthreads();

    if (PHASE == 1) {
        for (int i = tid; i < 128 * 32; i += 256) {
            int r = i >> 5, q = i & 31;
            float4 v = *(const float4*)(SF + r * 132 + q * 4);
            __nv_bfloat16 h0, l0, h1, l1, h2, l2, h3, l3;
            split2(v.x, h0, l0); split2(v.y, h1, l1); split2(v.z, h2, l2); split2(v.w, h3, l3);
            size_t drow = (size_t)seg * CAP + m0 + r;
            uint2 vh, vl;
            vh.x = ((uint32_t)__bfloat16_as_ushort(h1) << 16) | __bfloat16_as_ushort(h0);
            vh.y = ((uint32_t)__bfloat16_as_ushort(h3) << 16) | __bfloat16_as_ushort(h2);
            vl.x = ((uint32_t)__bfloat16_as_ushort(l1) << 16) | __bfloat16_as_ushort(l0);
            vl.y = ((uint32_t)__bfloat16_as_ushort(l3) << 16) | __bfloat16_as_ushort(l2);
            *(uint2*)(g_hh + drow * HH + n0 + q * 4) = vh;
            *(uint2*)(g_hl + drow * HH + n0 + q * 4) = vl;
        }
    } else {
        for (int i = tid; i < 128 * 32; i += 256) {
            int r = i >> 5, q = i & 31;
            float4 v = *(const float4*)(SF + r * 132 + q * 4);
            size_t drow = (size_t)seg * CAP + m0 + r;
            *(float4*)(g_y + drow * DM + n0 + q * 4) = v;
        }
    }
}

// ---------------- combine: out = shared + g0*e0 + g1*e1 ----------------------
__global__ void combine_k(float* __restrict__ out) {
    int t = blockIdx.x;
    int i = threadIdx.x;
    int e0 = t_ei[2 * t], e1 = t_ei[2 * t + 1];
    int s0 = t_si[2 * t], s1 = t_si[2 * t + 1];
    float g0 = t_gv[2 * t], g1 = t_gv[2 * t + 1];
    const float4* ys = (const float4*)(g_y + ((size_t)NE * CAP + t) * DM);
    const float4* y0 = (const float4*)(g_y + ((size_t)e0 * CAP + s0) * DM);
    const float4* y1 = (const float4*)(g_y + ((size_t)e1 * CAP + s1) * DM);
    float4* o = (float4*)(out + (size_t)t * DM);
    float4 a = ys[i], b = y0[i], c = y1[i];
    o[i] = make_float4(a.x + g0 * b.x + g1 * c.x,
                       a.y + g0 * b.y + g1 * c.y,
                       a.z + g0 * b.z + g1 * c.z,
                       a.w + g0 * b.w + g1 * c.w);
}

// ---------------------------------------------------------------------------
extern "C" void kernel_launch(void* const* d_in, const int* in_sizes, int n_in,
                              void* d_out, int out_size) {
    const float* x   = (const float*)d_in[0];
    const float* sw1 = (const float*)d_in[1];
    const float* sw2 = (const float*)d_in[2];
    const float* ew1 = (const float*)d_in[3];
    const float* ew2 = (const float*)d_in[4];
    const float* gw  = (const float*)d_in[5];
    float* out = (float*)d_out;

    cudaFuncSetAttribute(gemm_k<1>, cudaFuncAttributeMaxDynamicSharedMemorySize, SMEM_SZ);
    cudaFuncSetAttribute(gemm_k<2>, cudaFuncAttributeMaxDynamicSharedMemorySize, SMEM_SZ);

    reset_k<<<1, 32>>>();
    gate_k<<<(TT * 32) / 256, 256>>>(x, gw);
    wcvt_k<<<dim3(4096, NSEG, 2), 256>>>(sw1, sw2, ew1, ew2);
    gather_k<<<dim3(CAP, NSEG), 256>>>(x);
    gemm_k<1><<<dim3(HH / 128, CAP / 128, NSEG), 256, SMEM_SZ>>>();
    gemm_k<2><<<dim3(DM / 128, CAP / 128, NSEG), 256, SMEM_SZ>>>();
    combine_k<<<TT, 256>>>(out);
}

// round 5
// speedup vs baseline: 2.7767x; 1.0770x over previous
#include <cuda_runtime.h>
#include <cuda_bf16.h>
#include <math.h>
#include <stdint.h>

#define TT   4096
#define DM   1024
#define HH   4096
#define NE   8
#define NSEG 9
#define CAP  4096

// smem: per stage Ah(128x144) Al(128x144) Bh(256x144) Bl(256x144)
#define A_TILE_B 18432
#define B_TILE_B 36864
#define STAGE_B  110592
#define SMEM_SZ  221184

// ---------------- scratch (__device__ globals; allocation-free rule) -------
__device__ int   g_cnt[NSEG];
__device__ int   g_rowmap[NE * CAP];
__device__ float g_sgate[NE * CAP];

__device__ __align__(16) __nv_bfloat16 g_xh[(size_t)NSEG * CAP * DM];
__device__ __align__(16) __nv_bfloat16 g_xl[(size_t)NSEG * CAP * DM];
__device__ __align__(16) __nv_bfloat16 g_w1h[(size_t)NSEG * HH * DM];
__device__ __align__(16) __nv_bfloat16 g_w1l[(size_t)NSEG * HH * DM];
__device__ __align__(16) __nv_bfloat16 g_w2h[(size_t)NSEG * DM * HH];
__device__ __align__(16) __nv_bfloat16 g_w2l[(size_t)NSEG * DM * HH];
__device__ __align__(16) __nv_bfloat16 g_hh[(size_t)NSEG * CAP * HH];
__device__ __align__(16) __nv_bfloat16 g_hl[(size_t)NSEG * CAP * HH];

// ---------------- helpers ---------------------------------------------------
__device__ __forceinline__ uint32_t s2u(const void* p) {
    uint32_t a;
    asm("{ .reg .u64 t; cvta.to.shared.u64 t, %1; cvt.u32.u64 %0, t; }" : "=r"(a) : "l"(p));
    return a;
}
__device__ __forceinline__ void cpasync16(uint32_t dst, const void* src) {
    asm volatile("cp.async.cg.shared.global [%0], [%1], 16;" :: "r"(dst), "l"(src) : "memory");
}
__device__ __forceinline__ void cp_commit() { asm volatile("cp.async.commit_group;" ::: "memory"); }
template <int N> __device__ __forceinline__ void cp_wait() {
    asm volatile("cp.async.wait_group %0;" :: "n"(N) : "memory");
}
__device__ __forceinline__ void ldsm4(uint32_t* r, uint32_t a) {
    asm volatile("ldmatrix.sync.aligned.m8n8.x4.shared.b16 {%0,%1,%2,%3}, [%4];"
                 : "=r"(r[0]), "=r"(r[1]), "=r"(r[2]), "=r"(r[3]) : "r"(a));
}
__device__ __forceinline__ void ldsm2(uint32_t* r, uint32_t a) {
    asm volatile("ldmatrix.sync.aligned.m8n8.x2.shared.b16 {%0,%1}, [%2];"
                 : "=r"(r[0]), "=r"(r[1]) : "r"(a));
}
__device__ __forceinline__ void mma16816(float* c, const uint32_t* a, const uint32_t* b) {
    asm volatile("mma.sync.aligned.m16n8k16.row.col.f32.bf16.bf16.f32 "
                 "{%0,%1,%2,%3}, {%4,%5,%6,%7}, {%8,%9}, {%0,%1,%2,%3};"
                 : "+f"(c[0]), "+f"(c[1]), "+f"(c[2]), "+f"(c[3])
                 : "r"(a[0]), "r"(a[1]), "r"(a[2]), "r"(a[3]), "r"(b[0]), "r"(b[1]));
}
__device__ __forceinline__ void split2(float v, __nv_bfloat16& h, __nv_bfloat16& l) {
    h = __float2bfloat16(v);
    l = __float2bfloat16(v - __bfloat162float(h));
}

// ---------------- zero + reset ----------------------------------------------
__global__ void zero_k(float* __restrict__ out) {
    size_t i = (size_t)blockIdx.x * 256 + threadIdx.x;
    ((float4*)out)[i] = make_float4(0.f, 0.f, 0.f, 0.f);
}
__global__ void reset_k() {
    int i = threadIdx.x;
    if (i < NE) g_cnt[i] = 0;
    if (i == NE) g_cnt[NE] = TT;
}

// ---------------- gating: one warp per token --------------------------------
__global__ void gate_k(const float* __restrict__ x, const float* __restrict__ gw) {
    int gtid = blockIdx.x * blockDim.x + threadIdx.x;
    int t = gtid >> 5, lane = gtid & 31;
    if (t >= TT) return;
    const float* xr = x + (size_t)t * DM;
    float acc[NE];
#pragma unroll
    for (int e = 0; e < NE; e++) acc[e] = 0.f;
    for (int k = lane; k < DM; k += 32) {
        float xv = xr[k];
#pragma unroll
        for (int e = 0; e < NE; e++) acc[e] += xv * gw[e * DM + k];
    }
#pragma unroll
    for (int e = 0; e < NE; e++) {
#pragma unroll
        for (int o = 16; o > 0; o >>= 1) acc[e] += __shfl_xor_sync(0xffffffffu, acc[e], o);
    }
    if (lane == 0) {
        int i0 = 0; float v0 = acc[0];
#pragma unroll
        for (int e = 1; e < NE; e++) if (acc[e] > v0) { v0 = acc[e]; i0 = e; }
        int i1 = -1; float v1 = -1e30f;
#pragma unroll
        for (int e = 0; e < NE; e++) if (e != i0 && acc[e] > v1) { v1 = acc[e]; i1 = e; }
        float ex = expf(v1 - v0);
        float g0 = 1.f / (1.f + ex);
        float g1 = ex / (1.f + ex);
        int p0 = atomicAdd(&g_cnt[i0], 1);
        g_rowmap[i0 * CAP + p0] = t; g_sgate[i0 * CAP + p0] = g0;
        int p1 = atomicAdd(&g_cnt[i1], 1);
        g_rowmap[i1 * CAP + p1] = t; g_sgate[i1 * CAP + p1] = g1;
    }
}

// ---------------- weight convert fp32 -> bf16 hi/lo --------------------------
__global__ void wcvt_k(const float* __restrict__ sw1, const float* __restrict__ sw2,
                       const float* __restrict__ ew1, const float* __restrict__ ew2) {
    int seg = blockIdx.y, wsel = blockIdx.z;
    size_t segoff = (size_t)seg * HH * DM;
    size_t i4 = (size_t)blockIdx.x * 256 + threadIdx.x;
    const float* src;
    __nv_bfloat16 *dh, *dl;
    if (wsel == 0) {
        src = (seg == NE) ? sw1 : (ew1 + segoff);
        dh = g_w1h + segoff; dl = g_w1l + segoff;
    } else {
        src = (seg == NE) ? sw2 : (ew2 + segoff);
        dh = g_w2h + segoff; dl = g_w2l + segoff;
    }
    float4 v = ((const float4*)src)[i4];
    __nv_bfloat16 h0, l0, h1, l1, h2, l2, h3, l3;
    split2(v.x, h0, l0); split2(v.y, h1, l1); split2(v.z, h2, l2); split2(v.w, h3, l3);
    __nv_bfloat162* ph = (__nv_bfloat162*)(dh + i4 * 4);
    __nv_bfloat162* pl = (__nv_bfloat162*)(dl + i4 * 4);
    ph[0] = __nv_bfloat162{h0, h1}; ph[1] = __nv_bfloat162{h2, h3};
    pl[0] = __nv_bfloat162{l0, l1}; pl[1] = __nv_bfloat162{l2, l3};
}

// ---------------- gather + convert activations per segment -------------------
__global__ void gather_k(const float* __restrict__ x) {
    int seg = blockIdx.y, slot = blockIdx.x;
    int cnt = g_cnt[seg];
    int pad = (cnt + 127) & ~127;
    if (slot >= pad) return;
    size_t drow = ((size_t)seg * CAP + slot) * DM;
    int i = threadIdx.x;
    __nv_bfloat16 h0, l0, h1, l1, h2, l2, h3, l3;
    if (slot < cnt) {
        int tok = (seg == NE) ? slot : g_rowmap[seg * CAP + slot];
        float4 v = ((const float4*)(x + (size_t)tok * DM))[i];
        split2(v.x, h0, l0); split2(v.y, h1, l1); split2(v.z, h2, l2); split2(v.w, h3, l3);
    } else {
        h0 = l0 = h1 = l1 = h2 = l2 = h3 = l3 = __float2bfloat16(0.f);
    }
    __nv_bfloat162* ph = (__nv_bfloat162*)(g_xh + drow + (size_t)i * 4);
    __nv_bfloat162* pl = (__nv_bfloat162*)(g_xl + drow + (size_t)i * 4);
    ph[0] = __nv_bfloat162{h0, h1}; ph[1] = __nv_bfloat162{h2, h3};
    pl[0] = __nv_bfloat162{l0, l1}; pl[1] = __nv_bfloat162{l2, l3};
}

// ---------------- grouped GEMM, 128x256 CTA tile, warp tile 64x64 ------------
// PHASE 1: h = silu(x @ W1^T), K=1024 -> g_hh/g_hl
// PHASE 2: out[tok] += gate * (h @ W2^T), K=4096 (fused combine via atomics)
template <int PHASE>
__global__ __launch_bounds__(256, 1) void gemm_k(float* __restrict__ out) {
    constexpr int KLEN = (PHASE == 1) ? DM : HH;
    constexpr int NDIM = (PHASE == 1) ? HH : DM;
    constexpr int NC   = KLEN / 64;

    const int seg = blockIdx.z;
    const int cnt = g_cnt[seg];
    const int m0  = blockIdx.y * 128;
    if (m0 >= cnt) return;
    const int n0  = blockIdx.x * 256;

    extern __shared__ char smem[];
    const uint32_t sb = s2u(smem);

    const int tid  = threadIdx.x;
    const int lane = tid & 31;
    const int warp = tid >> 5;
    const int wm   = (warp & 1) * 64;    // warp m-base (2 warps over M)
    const int wn   = (warp >> 1) * 64;   // warp n-base (4 warps over N)

    const __nv_bfloat16* srcs[4];
    if (PHASE == 1) {
        srcs[0] = g_xh  + ((size_t)seg * CAP  + m0) * KLEN;
        srcs[1] = g_xl  + ((size_t)seg * CAP  + m0) * KLEN;
        srcs[2] = g_w1h + ((size_t)seg * NDIM + n0) * KLEN;
        srcs[3] = g_w1l + ((size_t)seg * NDIM + n0) * KLEN;
    } else {
        srcs[0] = g_hh  + ((size_t)seg * CAP  + m0) * KLEN;
        srcs[1] = g_hl  + ((size_t)seg * CAP  + m0) * KLEN;
        srcs[2] = g_w2h + ((size_t)seg * NDIM + n0) * KLEN;
        srcs[3] = g_w2l + ((size_t)seg * NDIM + n0) * KLEN;
    }

    auto issue = [&](int c) {
        uint32_t base = sb + (c & 1) * STAGE_B;
#pragma unroll
        for (int tI = 0; tI < 2; tI++) {                  // A tiles: 128 rows
            const __nv_bfloat16* s = srcs[tI];
#pragma unroll
            for (int it = 0; it < 4; it++) {
                int o = tid + it * 256;                   // 0..1023
                int row = o >> 3, q = o & 7;
                cpasync16(base + tI * A_TILE_B + row * 144 + q * 16,
                          s + (size_t)row * KLEN + c * 64 + q * 8);
            }
        }
#pragma unroll
        for (int tI = 0; tI < 2; tI++) {                  // B tiles: 256 rows
            const __nv_bfloat16* s = srcs[2 + tI];
#pragma unroll
            for (int it = 0; it < 8; it++) {
                int o = tid + it * 256;                   // 0..2047
                int row = o >> 3, q = o & 7;
                cpasync16(base + 2 * A_TILE_B + tI * B_TILE_B + row * 144 + q * 16,
                          s + (size_t)row * KLEN + c * 64 + q * 8);
            }
        }
        cp_commit();
    };

    float acc[4][8][4];
#pragma unroll
    for (int mi = 0; mi < 4; mi++)
#pragma unroll
        for (int ni = 0; ni < 8; ni++)
#pragma unroll
            for (int r = 0; r < 4; r++) acc[mi][ni][r] = 0.f;

    issue(0);

    for (int c = 0; c < NC; c++) {
        if (c + 1 < NC) { issue(c + 1); cp_wait<1>(); }
        else            { cp_wait<0>(); }
        __syncthreads();

        uint32_t Ah = sb + (c & 1) * STAGE_B;
        uint32_t Al = Ah + A_TILE_B;
        uint32_t Bh = Ah + 2 * A_TILE_B;
        uint32_t Bl = Bh + B_TILE_B;

#pragma unroll
        for (int ks = 0; ks < 4; ks++) {
            const uint32_t acol = ks * 32 + (lane >> 4) * 16;
            const uint32_t bcol = ks * 32 + ((lane >> 3) & 1) * 16;
            uint32_t ah[4][4], bh[8][2];
#pragma unroll
            for (int mi = 0; mi < 4; mi++)
                ldsm4(ah[mi], Ah + (wm + mi * 16 + (lane & 15)) * 144 + acol);
#pragma unroll
            for (int ni = 0; ni < 8; ni++)
                ldsm2(bh[ni], Bh + (wn + ni * 8 + (lane & 7)) * 144 + bcol);
#pragma unroll
            for (int mi = 0; mi < 4; mi++)
#pragma unroll
                for (int ni = 0; ni < 8; ni++) mma16816(acc[mi][ni], ah[mi], bh[ni]);
            {   // al * bh (al short-lived)
                uint32_t al[4][4];
#pragma unroll
                for (int mi = 0; mi < 4; mi++)
                    ldsm4(al[mi], Al + (wm + mi * 16 + (lane & 15)) * 144 + acol);
#pragma unroll
                for (int mi = 0; mi < 4; mi++)
#pragma unroll
                    for (int ni = 0; ni < 8; ni++) mma16816(acc[mi][ni], al[mi], bh[ni]);
            }
            {   // ah * bl (bl overwrites bh liveness)
                uint32_t bl[8][2];
#pragma unroll
                for (int ni = 0; ni < 8; ni++)
                    ldsm2(bl[ni], Bl + (wn + ni * 8 + (lane & 7)) * 144 + bcol);
#pragma unroll
                for (int mi = 0; mi < 4; mi++)
#pragma unroll
                    for (int ni = 0; ni < 8; ni++) mma16816(acc[mi][ni], ah[mi], bl[ni]);
            }
        }
        __syncthreads();
    }

    // ---- epilogue: regs -> smem (f32, stride 260) -> gmem ----
    float* SF = (float*)smem;
    int*   RI = (int*)(smem + 133120);
    float* GV = (float*)(smem + 133120 + 512);

#pragma unroll
    for (int mi = 0; mi < 4; mi++)
#pragma unroll
        for (int ni = 0; ni < 8; ni++)
#pragma unroll
            for (int r = 0; r < 4; r++) {
                int row = wm + mi * 16 + (lane >> 2) + (r >> 1) * 8;
                int col = wn + ni * 8 + (lane & 3) * 2 + (r & 1);
                float v = acc[mi][ni][r];
                if (PHASE == 1) v = v / (1.f + expf(-v));
                SF[row * 260 + col] = v;
            }
    if (PHASE == 2 && tid < 128) {
        int m = m0 + tid;
        if (seg == NE)      { RI[tid] = m; GV[tid] = 1.f; }
        else if (m < cnt)   { RI[tid] = g_rowmap[seg * CAP + m]; GV[tid] = g_sgate[seg * CAP + m]; }
        else                { RI[tid] = 0; GV[tid] = 0.f; }
    }
    __syncthreads();

    if (PHASE == 1) {
        for (int i = tid; i < 128 * 64; i += 256) {
            int r = i >> 6, q = i & 63;
            float4 v = *(const float4*)(SF + r * 260 + q * 4);
            __nv_bfloat16 h0, l0, h1, l1, h2, l2, h3, l3;
            split2(v.x, h0, l0); split2(v.y, h1, l1); split2(v.z, h2, l2); split2(v.w, h3, l3);
            size_t drow = (size_t)seg * CAP + m0 + r;
            uint2 vh, vl;
            vh.x = ((uint32_t)__bfloat16_as_ushort(h1) << 16) | __bfloat16_as_ushort(h0);
            vh.y = ((uint32_t)__bfloat16_as_ushort(h3) << 16) | __bfloat16_as_ushort(h2);
            vl.x = ((uint32_t)__bfloat16_as_ushort(l1) << 16) | __bfloat16_as_ushort(l0);
            vl.y = ((uint32_t)__bfloat16_as_ushort(l3) << 16) | __bfloat16_as_ushort(l2);
            *(uint2*)(g_hh + drow * HH + n0 + q * 4) = vh;
            *(uint2*)(g_hl + drow * HH + n0 + q * 4) = vl;
        }
    } else {
        for (int i = tid; i < 128 * 64; i += 256) {
            int r = i >> 6, q = i & 63;
            float4 v = *(const float4*)(SF + r * 260 + q * 4);
            float gv = GV[r];
            float* op = out + (size_t)RI[r] * DM + n0 + q * 4;
            atomicAdd(op + 0, gv * v.x);
            atomicAdd(op + 1, gv * v.y);
            atomicAdd(op + 2, gv * v.z);
            atomicAdd(op + 3, gv * v.w);
        }
    }
}

// ---------------------------------------------------------------------------
extern "C" void kernel_launch(void* const* d_in, const int* in_sizes, int n_in,
                              void* d_out, int out_size) {
    const float* x   = (const float*)d_in[0];
    const float* sw1 = (const float*)d_in[1];
    const float* sw2 = (const float*)d_in[2];
    const float* ew1 = (const float*)d_in[3];
    const float* ew2 = (const float*)d_in[4];
    const float* gw  = (const float*)d_in[5];
    float* out = (float*)d_out;

    cudaFuncSetAttribute(gemm_k<1>, cudaFuncAttributeMaxDynamicSharedMemorySize, SMEM_SZ);
    cudaFuncSetAttribute(gemm_k<2>, cudaFuncAttributeMaxDynamicSharedMemorySize, SMEM_SZ);

    zero_k<<<(TT * DM) / 1024, 256>>>(out);
    reset_k<<<1, 32>>>();
    gate_k<<<(TT * 32) / 256, 256>>>(x, gw);
    wcvt_k<<<dim3(4096, NSEG, 2), 256>>>(sw1, sw2, ew1, ew2);
    gather_k<<<dim3(CAP, NSEG), 256>>>(x);
    gemm_k<1><<<dim3(HH / 256, CAP / 128, NSEG), 256, SMEM_SZ>>>(out);
    gemm_k<2><<<dim3(DM / 256, CAP / 128, NSEG), 256, SMEM_SZ>>>(out);
}

// round 6
// speedup vs baseline: 5.7859x; 2.0838x over previous
#include <cuda_runtime.h>
#include <cuda_fp16.h>
#include <math.h>
#include <stdint.h>

#define TT   4096
#define DM   1024
#define HH   4096
#define NE   8
#define NSEG 9
#define CAP  4096

// smem: per stage A(128x144B) + B(256x144B); 3 stages
#define A_TILE_B 18432
#define B_TILE_B 36864
#define STAGE_B  55296
#define SMEM_SZ  165888

// ---------------- scratch (__device__ globals; allocation-free rule) -------
__device__ int   g_cnt[NSEG];
__device__ int   g_rowmap[NE * CAP];
__device__ float g_sgate[NE * CAP];

__device__ __align__(16) __half g_x [(size_t)NSEG * CAP * DM];
__device__ __align__(16) __half g_w1[(size_t)NSEG * HH * DM];
__device__ __align__(16) __half g_w2[(size_t)NSEG * DM * HH];
__device__ __align__(16) __half g_h [(size_t)NSEG * CAP * HH];

// ---------------- helpers ---------------------------------------------------
__device__ __forceinline__ uint32_t s2u(const void* p) {
    uint32_t a;
    asm("{ .reg .u64 t; cvta.to.shared.u64 t, %1; cvt.u32.u64 %0, t; }" : "=r"(a) : "l"(p));
    return a;
}
__device__ __forceinline__ void cpasync16(uint32_t dst, const void* src) {
    asm volatile("cp.async.cg.shared.global [%0], [%1], 16;" :: "r"(dst), "l"(src) : "memory");
}
__device__ __forceinline__ void cp_commit() { asm volatile("cp.async.commit_group;" ::: "memory"); }
template <int N> __device__ __forceinline__ void cp_wait() {
    asm volatile("cp.async.wait_group %0;" :: "n"(N) : "memory");
}
__device__ __forceinline__ void ldsm4(uint32_t* r, uint32_t a) {
    asm volatile("ldmatrix.sync.aligned.m8n8.x4.shared.b16 {%0,%1,%2,%3}, [%4];"
                 : "=r"(r[0]), "=r"(r[1]), "=r"(r[2]), "=r"(r[3]) : "r"(a));
}
__device__ __forceinline__ void ldsm2(uint32_t* r, uint32_t a) {
    asm volatile("ldmatrix.sync.aligned.m8n8.x2.shared.b16 {%0,%1}, [%2];"
                 : "=r"(r[0]), "=r"(r[1]) : "r"(a));
}
__device__ __forceinline__ void mma16816(float* c, const uint32_t* a, const uint32_t* b) {
    asm volatile("mma.sync.aligned.m16n8k16.row.col.f32.f16.f16.f32 "
                 "{%0,%1,%2,%3}, {%4,%5,%6,%7}, {%8,%9}, {%0,%1,%2,%3};"
                 : "+f"(c[0]), "+f"(c[1]), "+f"(c[2]), "+f"(c[3])
                 : "r"(a[0]), "r"(a[1]), "r"(a[2]), "r"(a[3]), "r"(b[0]), "r"(b[1]));
}

// ---------------- zero + reset ----------------------------------------------
__global__ void zero_k(float* __restrict__ out) {
    size_t i = (size_t)blockIdx.x * 256 + threadIdx.x;
    ((float4*)out)[i] = make_float4(0.f, 0.f, 0.f, 0.f);
}
__global__ void reset_k() {
    int i = threadIdx.x;
    if (i < NE) g_cnt[i] = 0;
    if (i == NE) g_cnt[NE] = TT;
}

// ---------------- gating: one warp per token --------------------------------
__global__ void gate_k(const float* __restrict__ x, const float* __restrict__ gw) {
    int gtid = blockIdx.x * blockDim.x + threadIdx.x;
    int t = gtid >> 5, lane = gtid & 31;
    if (t >= TT) return;
    const float* xr = x + (size_t)t * DM;
    float acc[NE];
#pragma unroll
    for (int e = 0; e < NE; e++) acc[e] = 0.f;
    for (int k = lane; k < DM; k += 32) {
        float xv = xr[k];
#pragma unroll
        for (int e = 0; e < NE; e++) acc[e] += xv * gw[e * DM + k];
    }
#pragma unroll
    for (int e = 0; e < NE; e++) {
#pragma unroll
        for (int o = 16; o > 0; o >>= 1) acc[e] += __shfl_xor_sync(0xffffffffu, acc[e], o);
    }
    if (lane == 0) {
        int i0 = 0; float v0 = acc[0];
#pragma unroll
        for (int e = 1; e < NE; e++) if (acc[e] > v0) { v0 = acc[e]; i0 = e; }
        int i1 = -1; float v1 = -1e30f;
#pragma unroll
        for (int e = 0; e < NE; e++) if (e != i0 && acc[e] > v1) { v1 = acc[e]; i1 = e; }
        float ex = expf(v1 - v0);
        float g0 = 1.f / (1.f + ex);
        float g1 = ex / (1.f + ex);
        int p0 = atomicAdd(&g_cnt[i0], 1);
        g_rowmap[i0 * CAP + p0] = t; g_sgate[i0 * CAP + p0] = g0;
        int p1 = atomicAdd(&g_cnt[i1], 1);
        g_rowmap[i1 * CAP + p1] = t; g_sgate[i1 * CAP + p1] = g1;
    }
}

// ---------------- weight convert fp32 -> fp16 --------------------------------
__global__ void wcvt_k(const float* __restrict__ sw1, const float* __restrict__ sw2,
                       const float* __restrict__ ew1, const float* __restrict__ ew2) {
    int seg = blockIdx.y, wsel = blockIdx.z;
    size_t segoff = (size_t)seg * HH * DM;
    size_t i4 = (size_t)blockIdx.x * 256 + threadIdx.x;
    const float* src;
    __half* dst;
    if (wsel == 0) { src = (seg == NE) ? sw1 : (ew1 + segoff); dst = g_w1 + segoff; }
    else           { src = (seg == NE) ? sw2 : (ew2 + segoff); dst = g_w2 + segoff; }
    float4 v = ((const float4*)src)[i4];
    __half2* p = (__half2*)(dst + i4 * 4);
    p[0] = __floats2half2_rn(v.x, v.y);
    p[1] = __floats2half2_rn(v.z, v.w);
}

// ---------------- gather + convert activations per segment -------------------
__global__ void gather_k(const float* __restrict__ x) {
    int seg = blockIdx.y, slot = blockIdx.x;
    int cnt = g_cnt[seg];
    int pad = (cnt + 127) & ~127;
    if (slot >= pad) return;
    size_t drow = ((size_t)seg * CAP + slot) * DM;
    int i = threadIdx.x;
    float4 v = make_float4(0.f, 0.f, 0.f, 0.f);
    if (slot < cnt) {
        int tok = (seg == NE) ? slot : g_rowmap[seg * CAP + slot];
        v = ((const float4*)(x + (size_t)tok * DM))[i];
    }
    __half2* p = (__half2*)(g_x + drow + (size_t)i * 4);
    p[0] = __floats2half2_rn(v.x, v.y);
    p[1] = __floats2half2_rn(v.z, v.w);
}

// ---------------- grouped GEMM, 128x256 CTA tile, warp tile 64x64, fp16 ------
// PHASE 1: h = silu(x @ W1^T), K=1024 -> g_h (fp16)
// PHASE 2: out[tok] += gate * (h @ W2^T), K=4096 (fused combine via atomics)
template <int PHASE>
__global__ __launch_bounds__(256, 1) void gemm_k(float* __restrict__ out) {
    constexpr int KLEN = (PHASE == 1) ? DM : HH;
    constexpr int NDIM = (PHASE == 1) ? HH : DM;
    constexpr int NC   = KLEN / 64;

    const int seg = blockIdx.z;
    const int cnt = g_cnt[seg];
    const int m0  = blockIdx.y * 128;
    if (m0 >= cnt) return;
    const int n0  = blockIdx.x * 256;

    extern __shared__ char smem[];
    const uint32_t sb = s2u(smem);

    const int tid  = threadIdx.x;
    const int lane = tid & 31;
    const int warp = tid >> 5;
    const int wm   = (warp & 1) * 64;    // warp m-base (2 warps over M)
    const int wn   = (warp >> 1) * 64;   // warp n-base (4 warps over N)

    const __half* Asrc, * Bsrc;
    if (PHASE == 1) {
        Asrc = g_x  + ((size_t)seg * CAP  + m0) * KLEN;
        Bsrc = g_w1 + ((size_t)seg * NDIM + n0) * KLEN;
    } else {
        Asrc = g_h  + ((size_t)seg * CAP  + m0) * KLEN;
        Bsrc = g_w2 + ((size_t)seg * NDIM + n0) * KLEN;
    }

    auto issue = [&](int c) {
        uint32_t base = sb + (c % 3) * STAGE_B;
#pragma unroll
        for (int it = 0; it < 4; it++) {                  // A: 128 rows x 8 chunks
            int o = tid + it * 256;                       // 0..1023
            int row = o >> 3, q = o & 7;
            cpasync16(base + row * 144 + q * 16,
                      Asrc + (size_t)row * KLEN + c * 64 + q * 8);
        }
#pragma unroll
        for (int it = 0; it < 8; it++) {                  // B: 256 rows x 8 chunks
            int o = tid + it * 256;                       // 0..2047
            int row = o >> 3, q = o & 7;
            cpasync16(base + A_TILE_B + row * 144 + q * 16,
                      Bsrc + (size_t)row * KLEN + c * 64 + q * 8);
        }
        cp_commit();
    };

    float acc[4][8][4];
#pragma unroll
    for (int mi = 0; mi < 4; mi++)
#pragma unroll
        for (int ni = 0; ni < 8; ni++)
#pragma unroll
            for (int r = 0; r < 4; r++) acc[mi][ni][r] = 0.f;

    issue(0);
    issue(1);

    for (int c = 0; c < NC; c++) {
        if (c + 2 < NC) issue(c + 2);
        else            cp_commit();                      // keep group count uniform
        cp_wait<2>();
        __syncthreads();

        uint32_t Ab = sb + (c % 3) * STAGE_B;
        uint32_t Bb = Ab + A_TILE_B;

#pragma unroll
        for (int ks = 0; ks < 4; ks++) {
            const uint32_t acol = ks * 32 + (lane >> 4) * 16;
            const uint32_t bcol = ks * 32 + ((lane >> 3) & 1) * 16;
            uint32_t ah[4][4], bh[8][2];
#pragma unroll
            for (int mi = 0; mi < 4; mi++)
                ldsm4(ah[mi], Ab + (wm + mi * 16 + (lane & 15)) * 144 + acol);
#pragma unroll
            for (int ni = 0; ni < 8; ni++)
                ldsm2(bh[ni], Bb + (wn + ni * 8 + (lane & 7)) * 144 + bcol);
#pragma unroll
            for (int mi = 0; mi < 4; mi++)
#pragma unroll
                for (int ni = 0; ni < 8; ni++) mma16816(acc[mi][ni], ah[mi], bh[ni]);
        }
        __syncthreads();
    }

    // ---- epilogue: regs -> smem (f32, stride 260) -> gmem ----
    float* SF = (float*)smem;
    int*   RI = (int*)(smem + 133120);
    float* GV = (float*)(smem + 133120 + 512);

#pragma unroll
    for (int mi = 0; mi < 4; mi++)
#pragma unroll
        for (int ni = 0; ni < 8; ni++)
#pragma unroll
            for (int r = 0; r < 4; r++) {
                int row = wm + mi * 16 + (lane >> 2) + (r >> 1) * 8;
                int col = wn + ni * 8 + (lane & 3) * 2 + (r & 1);
                float v = acc[mi][ni][r];
                if (PHASE == 1) v = v / (1.f + expf(-v));
                SF[row * 260 + col] = v;
            }
    if (PHASE == 2 && tid < 128) {
        int m = m0 + tid;
        if (seg == NE)      { RI[tid] = m; GV[tid] = 1.f; }
        else if (m < cnt)   { RI[tid] = g_rowmap[seg * CAP + m]; GV[tid] = g_sgate[seg * CAP + m]; }
        else                { RI[tid] = 0; GV[tid] = 0.f; }
    }
    __syncthreads();

    if (PHASE == 1) {
        for (int i = tid; i < 128 * 64; i += 256) {
            int r = i >> 6, q = i & 63;
            float4 v = *(const float4*)(SF + r * 260 + q * 4);
            size_t drow = (size_t)seg * CAP + m0 + r;
            __half2* p = (__half2*)(g_h + drow * HH + n0 + q * 4);
            p[0] = __floats2half2_rn(v.x, v.y);
            p[1] = __floats2half2_rn(v.z, v.w);
        }
    } else {
        for (int i = tid; i < 128 * 64; i += 256) {
            int r = i >> 6, q = i & 63;
            float4 v = *(const float4*)(SF + r * 260 + q * 4);
            float gv = GV[r];
            float* op = out + (size_t)RI[r] * DM + n0 + q * 4;
            atomicAdd(op + 0, gv * v.x);
            atomicAdd(op + 1, gv * v.y);
            atomicAdd(op + 2, gv * v.z);
            atomicAdd(op + 3, gv * v.w);
        }
    }
}

// ---------------------------------------------------------------------------
extern "C" void kernel_launch(void* const* d_in, const int* in_sizes, int n_in,
                              void* d_out, int out_size) {
    const float* x   = (const float*)d_in[0];
    const float* sw1 = (const float*)d_in[1];
    const float* sw2 = (const float*)d_in[2];
    const float* ew1 = (const float*)d_in[3];
    const float* ew2 = (const float*)d_in[4];
    const float* gw  = (const float*)d_in[5];
    float* out = (float*)d_out;

    cudaFuncSetAttribute(gemm_k<1>, cudaFuncAttributeMaxDynamicSharedMemorySize, SMEM_SZ);
    cudaFuncSetAttribute(gemm_k<2>, cudaFuncAttributeMaxDynamicSharedMemorySize, SMEM_SZ);

    zero_k<<<(TT * DM) / 1024, 256>>>(out);
    reset_k<<<1, 32>>>();
    gate_k<<<(TT * 32) / 256, 256>>>(x, gw);
    wcvt_k<<<dim3(4096, NSEG, 2), 256>>>(sw1, sw2, ew1, ew2);
    gather_k<<<dim3(CAP, NSEG), 256>>>(x);
    gemm_k<1><<<dim3(HH / 256, CAP / 128, NSEG), 256, SMEM_SZ>>>(out);
    gemm_k<2><<<dim3(DM / 256, CAP / 128, NSEG), 256, SMEM_SZ>>>(out);
}